// round 6
// baseline (speedup 1.0000x reference)
#include <cuda_runtime.h>
#include <cuda_bf16.h>
#include <stdint.h>

#define TT    512
#define TOPK  2
#define NE    8
#define NH    2816
#define ND    1024
#define NPAIR 1024

// Scratch (__device__ globals; zero-initialized, so clamped p=slot[0] is always safe)
__device__ int d_cnt[NE];
__device__ int d_slot[NE][NPAIR];
__device__ __align__(16) float          d_H1[(size_t)NPAIR * NH];
__device__ __align__(16) float          d_H3[(size_t)NPAIR * NH];
__device__ __align__(16) __nv_bfloat16  d_Ghi[(size_t)NPAIR * NH];
__device__ __align__(16) __nv_bfloat16  d_Glo[(size_t)NPAIR * NH];
__device__ __align__(16) __nv_bfloat16  d_xhi[TT * ND];
__device__ __align__(16) __nv_bfloat16  d_xlo[TT * ND];

// ---------------------------------------------------------------------------
__device__ __forceinline__ uint32_t smem_u32(const void* p) {
    uint32_t a;
    asm("{ .reg .u64 t; cvta.to.shared.u64 t, %1; cvt.u32.u64 %0, t; }" : "=r"(a) : "l"(p));
    return a;
}
__device__ __forceinline__ void ldsm4(uint32_t* r, uint32_t addr) {
    asm volatile("ldmatrix.sync.aligned.m8n8.x4.shared.b16 {%0,%1,%2,%3}, [%4];"
        : "=r"(r[0]), "=r"(r[1]), "=r"(r[2]), "=r"(r[3]) : "r"(addr));
}
__device__ __forceinline__ void mma16816(float* c, const uint32_t* a, const uint32_t* b) {
    asm volatile("mma.sync.aligned.m16n8k16.row.col.f32.bf16.bf16.f32 "
        "{%0,%1,%2,%3},{%4,%5,%6,%7},{%8,%9},{%0,%1,%2,%3};"
        : "+f"(c[0]), "+f"(c[1]), "+f"(c[2]), "+f"(c[3])
        : "r"(a[0]), "r"(a[1]), "r"(a[2]), "r"(a[3]), "r"(b[0]), "r"(b[1]));
}
__device__ __forceinline__ void cp16(uint32_t dst, const void* src) {
    asm volatile("cp.async.cg.shared.global [%0], [%1], 16;" :: "r"(dst), "l"(src) : "memory");
}
#define CP_COMMIT() asm volatile("cp.async.commit_group;" ::: "memory")
#define CP_WAIT0()  asm volatile("cp.async.wait_group 0;" ::: "memory")

__device__ __forceinline__ uint32_t pack2(__nv_bfloat16 e0, __nv_bfloat16 e1) {
    return (uint32_t)__bfloat16_as_ushort(e0) | ((uint32_t)__bfloat16_as_ushort(e1) << 16);
}
__device__ __forceinline__ void split_bf(float v, __nv_bfloat16& h, __nv_bfloat16& l) {
    h = __float2bfloat16(v);
    l = __float2bfloat16(v - __bfloat162float(h));
}

// ---------------------------------------------------------------------------
__global__ void route_kernel(const int* __restrict__ eidx) {
    __shared__ int s_cnt[NE];
    int tid = threadIdx.x;
    if (tid < NE) s_cnt[tid] = 0;
    __syncthreads();
    int e = eidx[tid];
    int slot = atomicAdd(&s_cnt[e], 1);
    d_slot[e][slot] = tid;
    __syncthreads();
    if (tid < NE) d_cnt[tid] = s_cnt[tid];
}

__global__ void prep_x(const float* __restrict__ x) {
    size_t i = ((size_t)blockIdx.x * blockDim.x + threadIdx.x) * 4;
    float4 v = *(const float4*)(x + i);
    __nv_bfloat16 h0, h1, h2, h3, l0, l1, l2, l3;
    split_bf(v.x, h0, l0); split_bf(v.y, h1, l1);
    split_bf(v.z, h2, l2); split_bf(v.w, h3, l3);
    *(uint2*)(d_xhi + i) = make_uint2(pack2(h0, h1), pack2(h2, h3));
    *(uint2*)(d_xlo + i) = make_uint2(pack2(l0, l1), pack2(l2, l3));
}

__global__ void gate_kernel() {
    size_t i = ((size_t)blockIdx.x * blockDim.x + threadIdx.x) * 4;
    float4 v1 = *(const float4*)(d_H1 + i);
    float4 v3 = *(const float4*)(d_H3 + i);
    float g0 = __fdividef(v1.x, 1.0f + __expf(-v1.x)) * v3.x;
    float g1 = __fdividef(v1.y, 1.0f + __expf(-v1.y)) * v3.y;
    float g2 = __fdividef(v1.z, 1.0f + __expf(-v1.z)) * v3.z;
    float g3 = __fdividef(v1.w, 1.0f + __expf(-v1.w)) * v3.w;
    __nv_bfloat16 h0, h1, h2, h3, l0, l1, l2, l3;
    split_bf(g0, h0, l0); split_bf(g1, h1, l1);
    split_bf(g2, h2, l2); split_bf(g3, h3, l3);
    *(uint2*)(d_Ghi + i) = make_uint2(pack2(h0, h1), pack2(h2, h3));
    *(uint2*)(d_Glo + i) = make_uint2(pack2(l0, l1), pack2(l2, l3));
}

// ---------------------------------------------------------------------------
// GEMM1: C[128 pairs x 64 h] = x_gathered . w{1|3}^T, K=1024 (16 chunks of 64)
// A via cp.async (pre-split bf16), B = weights fp32 -> bf16 hi/lo in regs.
// SMEM stage (48KB x2): AH(16K) AL(16K) BH(8K) BL(8K); header 1KB.
// ---------------------------------------------------------------------------
#define G1_STAGE 49152
#define G1_SMEM  (1024 + 2 * G1_STAGE)

__global__ __launch_bounds__(256, 2) void gemm1_mma(
    const float* __restrict__ w1, const float* __restrict__ w3)
{
    int z = blockIdx.z, e = z >> 1, f = z & 1;
    int cnt = d_cnt[e];
    int trow0 = blockIdx.y * 128;
    if (trow0 >= cnt) return;
    int col0 = blockIdx.x * 64;
    const float* w = f ? w3 : w1;
    float* dH = f ? d_H3 : d_H1;

    extern __shared__ char smem[];
    int* s_p   = (int*)smem;
    int* s_tok = (int*)(smem + 512);
    uint32_t sb = smem_u32(smem);

    int tid = threadIdx.x, lane = tid & 31, wid = tid >> 5;
    if (tid < 128) {
        int r = trow0 + tid;
        int p = (r < cnt) ? d_slot[e][r] : d_slot[e][0];
        s_p[tid] = p; s_tok[tid] = p >> 1;
    }
    __syncthreads();

    // A loader: row = tid>>1 (0..127), half = tid&1 (32 elems = 4 x 16B)
    int arow = tid >> 1, ahalf = tid & 1;
    uint32_t aswz = (uint32_t)((arow & 7) << 4);
    const __nv_bfloat16* xh = d_xhi + (size_t)s_tok[arow] * ND + ahalf * 32;
    const __nv_bfloat16* xl = d_xlo + (size_t)s_tok[arow] * ND + ahalf * 32;
    uint32_t aoff[4];
    #pragma unroll
    for (int j = 0; j < 4; j++)
        aoff[j] = (uint32_t)arow * 128 + (((uint32_t)(ahalf * 64 + j * 16)) ^ aswz);

    // B loader: row = tid>>2 (0..63 h), quarter = tid&3 (16 floats)
    int brow = tid >> 2, bq = tid & 3;
    uint32_t bswz = (uint32_t)((brow & 7) << 4);
    const float* wrow = w + ((size_t)e * NH + col0 + brow) * ND + bq * 16;
    uint32_t boff[4];
    #pragma unroll
    for (int j = 0; j < 4; j++)
        boff[j] = (uint32_t)brow * 128 + (((uint32_t)(bq * 32 + j * 8)) ^ bswz);

    float acc[2][4][4];
    #pragma unroll
    for (int a = 0; a < 2; a++)
        #pragma unroll
        for (int b = 0; b < 4; b++)
            #pragma unroll
            for (int c = 0; c < 4; c++) acc[a][b][c] = 0.0f;

    int wm = wid & 3, wn = wid >> 2;

    // prologue: cp.async A chunk 0 -> stage 0; LDG weights chunk 0
    float4 rb[4];
    {
        uint32_t base = sb + 1024;
        #pragma unroll
        for (int j = 0; j < 4; j++) {
            cp16(base + aoff[j], (const char*)xh + j * 16);
            cp16(base + 16384 + aoff[j], (const char*)xl + j * 16);
        }
        CP_COMMIT();
        #pragma unroll
        for (int j = 0; j < 4; j++) rb[j] = *(const float4*)(wrow + 4 * j);
    }

    #pragma unroll 1
    for (int kc = 0; kc < 16; kc++) {
        int s = kc & 1;
        char* stage = smem + 1024 + s * G1_STAGE;
        // store B(kc) -> stage s (convert fp32 -> hi/lo bf16)
        #pragma unroll
        for (int j = 0; j < 4; j++) {
            float4 v = rb[j];
            __nv_bfloat16 h0, h1, h2, h3, l0, l1, l2, l3;
            split_bf(v.x, h0, l0); split_bf(v.y, h1, l1);
            split_bf(v.z, h2, l2); split_bf(v.w, h3, l3);
            *(uint32_t*)(stage + 32768 + boff[j])     = pack2(h0, h1);
            *(uint32_t*)(stage + 32768 + boff[j] + 4) = pack2(h2, h3);
            *(uint32_t*)(stage + 40960 + boff[j])     = pack2(l0, l1);
            *(uint32_t*)(stage + 40960 + boff[j] + 4) = pack2(l2, l3);
        }
        CP_WAIT0();
        __syncthreads();
        if (kc < 15) {
            // cp.async A(kc+1) -> other stage; LDG weights(kc+1) (overlap MMA)
            uint32_t base = sb + 1024 + (s ^ 1) * G1_STAGE;
            const char* srcH = (const char*)(xh + (kc + 1) * 64);
            const char* srcL = (const char*)(xl + (kc + 1) * 64);
            #pragma unroll
            for (int j = 0; j < 4; j++) {
                cp16(base + aoff[j], srcH + j * 16);
                cp16(base + 16384 + aoff[j], srcL + j * 16);
            }
            CP_COMMIT();
            #pragma unroll
            for (int j = 0; j < 4; j++)
                rb[j] = *(const float4*)(wrow + (kc + 1) * 64 + 4 * j);
        }
        // MMA on stage s
        uint32_t uAH = sb + 1024 + s * G1_STAGE;
        uint32_t uAL = uAH + 16384;
        uint32_t uBH = uAH + 32768;
        uint32_t uBL = uAH + 40960;
        #pragma unroll
        for (int ks = 0; ks < 4; ks++) {
            uint32_t Ah[2][4], Al[2][4], Bh[2][4], Bl[2][4];
            int kb = ks * 32;
            #pragma unroll
            for (int mi = 0; mi < 2; mi++) {
                int row = wm * 32 + mi * 16 + (lane & 15);
                uint32_t b = (uint32_t)(kb + ((lane >> 4) << 4));
                uint32_t off = (uint32_t)row * 128 + (b ^ (uint32_t)((row & 7) << 4));
                ldsm4(Ah[mi], uAH + off);
                ldsm4(Al[mi], uAL + off);
            }
            #pragma unroll
            for (int nb = 0; nb < 2; nb++) {
                int row = wn * 32 + nb * 16 + (lane & 7) + (((lane >> 4) & 1) << 3);
                uint32_t b = (uint32_t)(kb + (((lane >> 3) & 1) << 4));
                uint32_t off = (uint32_t)row * 128 + (b ^ (uint32_t)((row & 7) << 4));
                ldsm4(Bh[nb], uBH + off);
                ldsm4(Bl[nb], uBL + off);
            }
            #pragma unroll
            for (int mi = 0; mi < 2; mi++)
                #pragma unroll
                for (int nb = 0; nb < 2; nb++) {
                    mma16816(acc[mi][2 * nb],     Ah[mi], &Bh[nb][0]);
                    mma16816(acc[mi][2 * nb],     Ah[mi], &Bl[nb][0]);
                    mma16816(acc[mi][2 * nb],     Al[mi], &Bh[nb][0]);
                    mma16816(acc[mi][2 * nb + 1], Ah[mi], &Bh[nb][2]);
                    mma16816(acc[mi][2 * nb + 1], Ah[mi], &Bl[nb][2]);
                    mma16816(acc[mi][2 * nb + 1], Al[mi], &Bh[nb][2]);
                }
        }
    }

    // epilogue
    int cntLoc = cnt - trow0; if (cntLoc > 128) cntLoc = 128;
    #pragma unroll
    for (int mi = 0; mi < 2; mi++) {
        int r0 = wm * 32 + mi * 16 + (lane >> 2);
        int r1 = r0 + 8;
        #pragma unroll
        for (int ni = 0; ni < 4; ni++) {
            int col = col0 + wn * 32 + ni * 8 + (lane & 3) * 2;
            if (r0 < cntLoc)
                *(float2*)&dH[(size_t)s_p[r0] * NH + col] =
                    make_float2(acc[mi][ni][0], acc[mi][ni][1]);
            if (r1 < cntLoc)
                *(float2*)&dH[(size_t)s_p[r1] * NH + col] =
                    make_float2(acc[mi][ni][2], acc[mi][ni][3]);
        }
    }
}

// ---------------------------------------------------------------------------
// GEMM2: C[64 pairs x 64 d] = G . w2, K=2816 (44 chunks of 64)
// A = Ghi/Glo via cp.async; B = w2 fp32 transposed to K-major in conversion.
// SMEM stage (32KB x2): AH(8K) AL(8K) BH(8K) BL(8K); header 512B.
// ---------------------------------------------------------------------------
#define G2_STAGE 32768
#define G2_SMEM  (512 + 2 * G2_STAGE)

__global__ __launch_bounds__(256, 2) void gemm2_mma(
    const float* __restrict__ w2, float* __restrict__ out)
{
    int e = blockIdx.z;
    int cnt = d_cnt[e];
    int trow0 = blockIdx.y * 64;
    if (trow0 >= cnt) return;
    int col0 = blockIdx.x * 64;

    extern __shared__ char smem[];
    int* s_p = (int*)smem;
    uint32_t sb = smem_u32(smem);

    int tid = threadIdx.x, lane = tid & 31, wid = tid >> 5;
    if (tid < 64) {
        int r = trow0 + tid;
        s_p[tid] = (r < cnt) ? d_slot[e][r] : d_slot[e][0];
    }
    __syncthreads();

    // A loader: row = tid>>2 (0..63), quarter = tid&3 (16 elems = 2 x 16B)
    int arow = tid >> 2, aq = tid & 3;
    uint32_t aswz = (uint32_t)((arow & 7) << 4);
    const __nv_bfloat16* gh = d_Ghi + (size_t)s_p[arow] * NH + aq * 16;
    const __nv_bfloat16* gl = d_Glo + (size_t)s_p[arow] * NH + aq * 16;
    uint32_t aoff[2];
    #pragma unroll
    for (int j = 0; j < 2; j++)
        aoff[j] = (uint32_t)arow * 128 + (((uint32_t)(aq * 32 + j * 16)) ^ aswz);

    // B loader: h-pair (tid&31)*2, d-group (tid>>5)*8
    int h = (tid & 31) * 2;
    int d0 = (tid >> 5) * 8;
    const float* bp = w2 + ((size_t)e * NH + h) * ND + col0 + d0;
    uint32_t bboff[8];
    #pragma unroll
    for (int j = 0; j < 2; j++)
        #pragma unroll
        for (int m = 0; m < 4; m++) {
            int d = d0 + 4 * j + m;
            bboff[4 * j + m] =
                (uint32_t)d * 128 + (((uint32_t)(h * 2)) ^ (uint32_t)((d & 7) << 4));
        }

    float acc[2][2][4];
    #pragma unroll
    for (int a = 0; a < 2; a++)
        #pragma unroll
        for (int b = 0; b < 2; b++)
            #pragma unroll
            for (int c = 0; c < 4; c++) acc[a][b][c] = 0.0f;

    int wm = wid & 1, wn = wid >> 1;   // wm: 2 x 32 rows, wn: 4 x 16 cols

    float4 rb0[2], rb1[2];
    {
        uint32_t base = sb + 512;
        #pragma unroll
        for (int j = 0; j < 2; j++) {
            cp16(base + aoff[j], (const char*)gh + j * 16);
            cp16(base + 8192 + aoff[j], (const char*)gl + j * 16);
        }
        CP_COMMIT();
        #pragma unroll
        for (int j = 0; j < 2; j++) {
            rb0[j] = *(const float4*)(bp + 4 * j);
            rb1[j] = *(const float4*)(bp + ND + 4 * j);
        }
    }

    #pragma unroll 1
    for (int kc = 0; kc < 44; kc++) {
        int s = kc & 1;
        char* stage = smem + 512 + s * G2_STAGE;
        // store B(kc): transpose + convert
        #pragma unroll
        for (int j = 0; j < 2; j++) {
            float va[4] = { rb0[j].x, rb0[j].y, rb0[j].z, rb0[j].w };
            float vb[4] = { rb1[j].x, rb1[j].y, rb1[j].z, rb1[j].w };
            #pragma unroll
            for (int m = 0; m < 4; m++) {
                __nv_bfloat16 ha, la, hb, lb;
                split_bf(va[m], ha, la);
                split_bf(vb[m], hb, lb);
                uint32_t off = bboff[4 * j + m];
                *(uint32_t*)(stage + 16384 + off) = pack2(ha, hb);
                *(uint32_t*)(stage + 24576 + off) = pack2(la, lb);
            }
        }
        CP_WAIT0();
        __syncthreads();
        if (kc < 43) {
            uint32_t base = sb + 512 + (s ^ 1) * G2_STAGE;
            const char* srcH = (const char*)(gh + (kc + 1) * 64);
            const char* srcL = (const char*)(gl + (kc + 1) * 64);
            #pragma unroll
            for (int j = 0; j < 2; j++) {
                cp16(base + aoff[j], srcH + j * 16);
                cp16(base + 8192 + aoff[j], srcL + j * 16);
            }
            CP_COMMIT();
            const float* bpn = bp + (size_t)(kc + 1) * 64 * ND;
            #pragma unroll
            for (int j = 0; j < 2; j++) {
                rb0[j] = *(const float4*)(bpn + 4 * j);
                rb1[j] = *(const float4*)(bpn + ND + 4 * j);
            }
        }
        // MMA on stage s
        uint32_t uAH = sb + 512 + s * G2_STAGE;
        uint32_t uAL = uAH + 8192;
        uint32_t uBH = uAH + 16384;
        uint32_t uBL = uAH + 24576;
        #pragma unroll
        for (int ks = 0; ks < 4; ks++) {
            uint32_t Ah[2][4], Al[2][4], Bh[4], Bl[4];
            int kb = ks * 32;
            #pragma unroll
            for (int mi = 0; mi < 2; mi++) {
                int row = wm * 32 + mi * 16 + (lane & 15);
                uint32_t b = (uint32_t)(kb + ((lane >> 4) << 4));
                uint32_t off = (uint32_t)row * 128 + (b ^ (uint32_t)((row & 7) << 4));
                ldsm4(Ah[mi], uAH + off);
                ldsm4(Al[mi], uAL + off);
            }
            {
                int row = wn * 16 + (lane & 7) + (((lane >> 4) & 1) << 3);
                uint32_t b = (uint32_t)(kb + (((lane >> 3) & 1) << 4));
                uint32_t off = (uint32_t)row * 128 + (b ^ (uint32_t)((row & 7) << 4));
                ldsm4(Bh, uBH + off);
                ldsm4(Bl, uBL + off);
            }
            #pragma unroll
            for (int mi = 0; mi < 2; mi++) {
                mma16816(acc[mi][0], Ah[mi], &Bh[0]);
                mma16816(acc[mi][0], Ah[mi], &Bl[0]);
                mma16816(acc[mi][0], Al[mi], &Bh[0]);
                mma16816(acc[mi][1], Ah[mi], &Bh[2]);
                mma16816(acc[mi][1], Ah[mi], &Bl[2]);
                mma16816(acc[mi][1], Al[mi], &Bh[2]);
            }
        }
    }

    int cntLoc = cnt - trow0; if (cntLoc > 64) cntLoc = 64;
    #pragma unroll
    for (int mi = 0; mi < 2; mi++) {
        int r0 = wm * 32 + mi * 16 + (lane >> 2);
        int r1 = r0 + 8;
        #pragma unroll
        for (int ni = 0; ni < 2; ni++) {
            int col = col0 + wn * 16 + ni * 8 + (lane & 3) * 2;
            if (r0 < cntLoc)
                *(float2*)&out[(size_t)s_p[r0] * ND + col] =
                    make_float2(acc[mi][ni][0], acc[mi][ni][1]);
            if (r1 < cntLoc)
                *(float2*)&out[(size_t)s_p[r1] * ND + col] =
                    make_float2(acc[mi][ni][2], acc[mi][ni][3]);
        }
    }
}

// ---------------------------------------------------------------------------
extern "C" void kernel_launch(void* const* d_in, const int* in_sizes, int n_in,
                              void* d_out, int out_size) {
    const float* x    = (const float*)d_in[0];
    const int*   eidx = (const int*)d_in[1];   // int32 (JAX default int)
    const float* w1   = (const float*)d_in[2];
    const float* w2   = (const float*)d_in[3];
    const float* w3   = (const float*)d_in[4];
    float*       out  = (float*)d_out;

    static bool attr_done = false;
    if (!attr_done) {
        cudaFuncSetAttribute(gemm1_mma, cudaFuncAttributeMaxDynamicSharedMemorySize, G1_SMEM);
        cudaFuncSetAttribute(gemm2_mma, cudaFuncAttributeMaxDynamicSharedMemorySize, G2_SMEM);
        attr_done = true;
    }

    route_kernel<<<1, NPAIR>>>(eidx);
    prep_x<<<(TT * ND / 4) / 256, 256>>>(x);

    dim3 g1(NH / 64, NPAIR / 128, NE * 2);   // 44 x 8 x 16
    gemm1_mma<<<g1, 256, G1_SMEM>>>(w1, w3);

    gate_kernel<<<(int)(((size_t)NPAIR * NH / 4) / 256), 256>>>();

    dim3 g2(ND / 64, NPAIR / 64, NE);        // 16 x 16 x 8
    gemm2_mma<<<g2, 256, G2_SMEM>>>(w2, out);
}

// round 7
// speedup vs baseline: 1.0754x; 1.0754x over previous
#include <cuda_runtime.h>
#include <cuda_bf16.h>
#include <stdint.h>

#define TT    512
#define TOPK  2
#define NE    8
#define NH    2816
#define ND    1024
#define NPAIR 1024

// Scratch
__device__ int d_cnt[NE];
__device__ int d_slot[NE][NPAIR];
__device__ __align__(16) float          d_H1[(size_t)NPAIR * NH];
__device__ __align__(16) float          d_H3[(size_t)NPAIR * NH];
__device__ __align__(16) __nv_bfloat16  d_Ghi[(size_t)NPAIR * NH];
__device__ __align__(16) __nv_bfloat16  d_Glo[(size_t)NPAIR * NH];
__device__ __align__(16) __nv_bfloat16  d_xhi[TT * ND];
__device__ __align__(16) __nv_bfloat16  d_xlo[TT * ND];

// ---------------------------------------------------------------------------
__device__ __forceinline__ uint32_t smem_u32(const void* p) {
    uint32_t a;
    asm("{ .reg .u64 t; cvta.to.shared.u64 t, %1; cvt.u32.u64 %0, t; }" : "=r"(a) : "l"(p));
    return a;
}
__device__ __forceinline__ void ldsm4(uint32_t* r, uint32_t addr) {
    asm volatile("ldmatrix.sync.aligned.m8n8.x4.shared.b16 {%0,%1,%2,%3}, [%4];"
        : "=r"(r[0]), "=r"(r[1]), "=r"(r[2]), "=r"(r[3]) : "r"(addr));
}
__device__ __forceinline__ void mma16816(float* c, const uint32_t* a, const uint32_t* b) {
    asm volatile("mma.sync.aligned.m16n8k16.row.col.f32.bf16.bf16.f32 "
        "{%0,%1,%2,%3},{%4,%5,%6,%7},{%8,%9},{%0,%1,%2,%3};"
        : "+f"(c[0]), "+f"(c[1]), "+f"(c[2]), "+f"(c[3])
        : "r"(a[0]), "r"(a[1]), "r"(a[2]), "r"(a[3]), "r"(b[0]), "r"(b[1]));
}
__device__ __forceinline__ void cp16(uint32_t dst, const void* src) {
    asm volatile("cp.async.cg.shared.global [%0], [%1], 16;" :: "r"(dst), "l"(src) : "memory");
}
#define CP_COMMIT() asm volatile("cp.async.commit_group;" ::: "memory")
#define CP_WAIT0()  asm volatile("cp.async.wait_group 0;" ::: "memory")

__device__ __forceinline__ uint32_t pack2(__nv_bfloat16 e0, __nv_bfloat16 e1) {
    return (uint32_t)__bfloat16_as_ushort(e0) | ((uint32_t)__bfloat16_as_ushort(e1) << 16);
}
__device__ __forceinline__ void split_bf(float v, __nv_bfloat16& h, __nv_bfloat16& l) {
    h = __float2bfloat16(v);
    l = __float2bfloat16(v - __bfloat162float(h));
}

// ---------------------------------------------------------------------------
__global__ void route_kernel(const int* __restrict__ eidx) {
    __shared__ int s_cnt[NE];
    int tid = threadIdx.x;
    if (tid < NE) s_cnt[tid] = 0;
    __syncthreads();
    int e = eidx[tid];
    int slot = atomicAdd(&s_cnt[e], 1);
    d_slot[e][slot] = tid;
    __syncthreads();
    if (tid < NE) d_cnt[tid] = s_cnt[tid];
}

__global__ void dummy_kernel() {}

__global__ void prep_x(const float* __restrict__ x) {
    size_t i = ((size_t)blockIdx.x * blockDim.x + threadIdx.x) * 4;
    float4 v = *(const float4*)(x + i);
    __nv_bfloat16 h0, h1, h2, h3, l0, l1, l2, l3;
    split_bf(v.x, h0, l0); split_bf(v.y, h1, l1);
    split_bf(v.z, h2, l2); split_bf(v.w, h3, l3);
    *(uint2*)(d_xhi + i) = make_uint2(pack2(h0, h1), pack2(h2, h3));
    *(uint2*)(d_xlo + i) = make_uint2(pack2(l0, l1), pack2(l2, l3));
}

__global__ void gate_kernel() {
    size_t i = ((size_t)blockIdx.x * blockDim.x + threadIdx.x) * 4;
    float4 v1 = *(const float4*)(d_H1 + i);
    float4 v3 = *(const float4*)(d_H3 + i);
    float g0 = __fdividef(v1.x, 1.0f + __expf(-v1.x)) * v3.x;
    float g1 = __fdividef(v1.y, 1.0f + __expf(-v1.y)) * v3.y;
    float g2 = __fdividef(v1.z, 1.0f + __expf(-v1.z)) * v3.z;
    float g3 = __fdividef(v1.w, 1.0f + __expf(-v1.w)) * v3.w;
    __nv_bfloat16 h0, h1, h2, h3, l0, l1, l2, l3;
    split_bf(g0, h0, l0); split_bf(g1, h1, l1);
    split_bf(g2, h2, l2); split_bf(g3, h3, l3);
    *(uint2*)(d_Ghi + i) = make_uint2(pack2(h0, h1), pack2(h2, h3));
    *(uint2*)(d_Glo + i) = make_uint2(pack2(l0, l1), pack2(l2, l3));
}

// ---------------------------------------------------------------------------
// GEMM1: C[128 pairs x 128 h] = x_gathered . w{1|3}^T, K=1024 (16 chunks of 64)
// Double-buffered stages of 64KB: AH(16K) AL(16K) BH(16K) BL(16K).
// A (pre-split bf16) via cp.async; B (weights) fp32 -> bf16 hi/lo in regs.
// ---------------------------------------------------------------------------
#define G1_STAGE 65536
#define G1_SMEM  (1024 + 2 * G1_STAGE)   // 132096

__global__ __launch_bounds__(256) void gemm1_mma(
    const float* __restrict__ w1, const float* __restrict__ w3)
{
    int z = blockIdx.z, e = z >> 1, f = z & 1;
    int cnt = d_cnt[e];
    int trow0 = blockIdx.y * 128;
    if (trow0 >= cnt) return;
    int col0 = blockIdx.x * 128;
    const float* w = f ? w3 : w1;
    float* dH = f ? d_H3 : d_H1;

    extern __shared__ char smem[];
    int* s_p   = (int*)smem;
    int* s_tok = (int*)(smem + 512);
    uint32_t sb = smem_u32(smem);

    int tid = threadIdx.x, lane = tid & 31, wid = tid >> 5;
    if (tid < 128) {
        int r = trow0 + tid;
        int p = (r < cnt) ? d_slot[e][r] : d_slot[e][0];
        s_p[tid] = p; s_tok[tid] = p >> 1;
    }
    __syncthreads();

    // A loader: row = tid>>1 (0..127), half = tid&1 (32 elems = 4 x 16B)
    int arow = tid >> 1, ahalf = tid & 1;
    uint32_t aswz = (uint32_t)((arow & 7) << 4);
    const __nv_bfloat16* xh = d_xhi + (size_t)s_tok[arow] * ND + ahalf * 32;
    const __nv_bfloat16* xl = d_xlo + (size_t)s_tok[arow] * ND + ahalf * 32;
    uint32_t aoff[4];
    #pragma unroll
    for (int j = 0; j < 4; j++)
        aoff[j] = (uint32_t)arow * 128 + (((uint32_t)(ahalf * 64 + j * 16)) ^ aswz);

    // B loader: row = tid>>1 (0..127 h), half = tid&1 (32 floats = 8 float4)
    const float* wrow = w + ((size_t)e * NH + col0 + arow) * ND + ahalf * 32;
    uint32_t boff[8];
    #pragma unroll
    for (int j = 0; j < 8; j++)
        boff[j] = (uint32_t)arow * 128 + (((uint32_t)(ahalf * 64 + j * 8)) ^ aswz);

    float acc[2][8][4];
    #pragma unroll
    for (int a = 0; a < 2; a++)
        #pragma unroll
        for (int b = 0; b < 8; b++)
            #pragma unroll
            for (int c = 0; c < 4; c++) acc[a][b][c] = 0.0f;

    int wm = wid & 3, wn = wid >> 2;

    // prologue: cp.async A(0) -> stage 0, LDG weights(0)
    float4 rb[8];
    {
        uint32_t base = sb + 1024;
        #pragma unroll
        for (int j = 0; j < 4; j++) {
            cp16(base + aoff[j], (const char*)xh + j * 16);
            cp16(base + 16384 + aoff[j], (const char*)xl + j * 16);
        }
        CP_COMMIT();
        #pragma unroll
        for (int j = 0; j < 8; j++) rb[j] = *(const float4*)(wrow + 4 * j);
    }

    #pragma unroll 1
    for (int kc = 0; kc < 16; kc++) {
        int s = kc & 1;
        char* stage = smem + 1024 + s * G1_STAGE;
        // store B(kc) -> stage s
        #pragma unroll
        for (int j = 0; j < 8; j++) {
            float4 v = rb[j];
            __nv_bfloat16 h0, h1, h2, h3, l0, l1, l2, l3;
            split_bf(v.x, h0, l0); split_bf(v.y, h1, l1);
            split_bf(v.z, h2, l2); split_bf(v.w, h3, l3);
            *(uint32_t*)(stage + 32768 + boff[j])     = pack2(h0, h1);
            *(uint32_t*)(stage + 32768 + boff[j] + 4) = pack2(h2, h3);
            *(uint32_t*)(stage + 49152 + boff[j])     = pack2(l0, l1);
            *(uint32_t*)(stage + 49152 + boff[j] + 4) = pack2(l2, l3);
        }
        CP_WAIT0();
        __syncthreads();
        if (kc < 15) {
            // overlap with MMA(kc): cp.async A(kc+1) -> other stage, LDG w(kc+1)
            uint32_t base = sb + 1024 + (s ^ 1) * G1_STAGE;
            const char* srcH = (const char*)(xh + (kc + 1) * 64);
            const char* srcL = (const char*)(xl + (kc + 1) * 64);
            #pragma unroll
            for (int j = 0; j < 4; j++) {
                cp16(base + aoff[j], srcH + j * 16);
                cp16(base + 16384 + aoff[j], srcL + j * 16);
            }
            CP_COMMIT();
            #pragma unroll
            for (int j = 0; j < 8; j++)
                rb[j] = *(const float4*)(wrow + (kc + 1) * 64 + 4 * j);
        }
        // MMA on stage s
        uint32_t uAH = sb + 1024 + s * G1_STAGE;
        uint32_t uAL = uAH + 16384;
        uint32_t uBH = uAH + 32768;
        uint32_t uBL = uAH + 49152;
        #pragma unroll
        for (int ks = 0; ks < 4; ks++) {
            uint32_t Ah[2][4], Al[2][4], Bh[4][4], Bl[4][4];
            int kb = ks * 32;
            #pragma unroll
            for (int mi = 0; mi < 2; mi++) {
                int row = wm * 32 + mi * 16 + (lane & 15);
                uint32_t b = (uint32_t)(kb + ((lane >> 4) << 4));
                uint32_t off = (uint32_t)row * 128 + (b ^ (uint32_t)((row & 7) << 4));
                ldsm4(Ah[mi], uAH + off);
                ldsm4(Al[mi], uAL + off);
            }
            #pragma unroll
            for (int nb = 0; nb < 4; nb++) {
                int row = wn * 64 + nb * 16 + (lane & 7) + (((lane >> 4) & 1) << 3);
                uint32_t b = (uint32_t)(kb + (((lane >> 3) & 1) << 4));
                uint32_t off = (uint32_t)row * 128 + (b ^ (uint32_t)((row & 7) << 4));
                ldsm4(Bh[nb], uBH + off);
                ldsm4(Bl[nb], uBL + off);
            }
            #pragma unroll
            for (int mi = 0; mi < 2; mi++)
                #pragma unroll
                for (int nb = 0; nb < 4; nb++) {
                    mma16816(acc[mi][2 * nb],     Ah[mi], &Bh[nb][0]);
                    mma16816(acc[mi][2 * nb],     Ah[mi], &Bl[nb][0]);
                    mma16816(acc[mi][2 * nb],     Al[mi], &Bh[nb][0]);
                    mma16816(acc[mi][2 * nb + 1], Ah[mi], &Bh[nb][2]);
                    mma16816(acc[mi][2 * nb + 1], Ah[mi], &Bl[nb][2]);
                    mma16816(acc[mi][2 * nb + 1], Al[mi], &Bh[nb][2]);
                }
        }
    }

    // epilogue
    int cntLoc = cnt - trow0; if (cntLoc > 128) cntLoc = 128;
    #pragma unroll
    for (int mi = 0; mi < 2; mi++) {
        int r0 = wm * 32 + mi * 16 + (lane >> 2);
        int r1 = r0 + 8;
        #pragma unroll
        for (int ni = 0; ni < 8; ni++) {
            int col = col0 + wn * 64 + ni * 8 + (lane & 3) * 2;
            if (r0 < cntLoc)
                *(float2*)&dH[(size_t)s_p[r0] * NH + col] =
                    make_float2(acc[mi][ni][0], acc[mi][ni][1]);
            if (r1 < cntLoc)
                *(float2*)&dH[(size_t)s_p[r1] * NH + col] =
                    make_float2(acc[mi][ni][2], acc[mi][ni][3]);
        }
    }
}

// ---------------------------------------------------------------------------
// GEMM2: C[128 pairs x 64 d] = G . w2, K=2816 (44 chunks of 64)
// Double-buffered 48KB stages: AH(16K) AL(16K) BH(8K) BL(8K).
// A = Ghi/Glo via cp.async; B = w2 transposed to K-major in conversion store.
// ---------------------------------------------------------------------------
#define G2_STAGE 49152
#define G2_SMEM  (512 + 2 * G2_STAGE)   // 98816

__global__ __launch_bounds__(256) void gemm2_mma(
    const float* __restrict__ w2, float* __restrict__ out)
{
    int e = blockIdx.z;
    int cnt = d_cnt[e];
    int trow0 = blockIdx.y * 128;
    if (trow0 >= cnt) return;
    int col0 = blockIdx.x * 64;

    extern __shared__ char smem[];
    int* s_p = (int*)smem;
    uint32_t sb = smem_u32(smem);

    int tid = threadIdx.x, lane = tid & 31, wid = tid >> 5;
    if (tid < 128) {
        int r = trow0 + tid;
        s_p[tid] = (r < cnt) ? d_slot[e][r] : d_slot[e][0];
    }
    __syncthreads();

    // A loader: row = tid>>1 (0..127), half = tid&1 (32 elems = 4 x 16B)
    int arow = tid >> 1, ahalf = tid & 1;
    uint32_t aswz = (uint32_t)((arow & 7) << 4);
    const __nv_bfloat16* gh = d_Ghi + (size_t)s_p[arow] * NH + ahalf * 32;
    const __nv_bfloat16* gl = d_Glo + (size_t)s_p[arow] * NH + ahalf * 32;
    uint32_t aoff[4];
    #pragma unroll
    for (int j = 0; j < 4; j++)
        aoff[j] = (uint32_t)arow * 128 + (((uint32_t)(ahalf * 64 + j * 16)) ^ aswz);

    // B loader: h-pair (tid&31)*2, d-group (tid>>5)*8
    int h = (tid & 31) * 2;
    int d0 = (tid >> 5) * 8;
    const float* bp = w2 + ((size_t)e * NH + h) * ND + col0 + d0;
    uint32_t bboff[8];
    #pragma unroll
    for (int j = 0; j < 2; j++)
        #pragma unroll
        for (int m = 0; m < 4; m++) {
            int d = d0 + 4 * j + m;
            bboff[4 * j + m] =
                (uint32_t)d * 128 + (((uint32_t)(h * 2)) ^ (uint32_t)((d & 7) << 4));
        }

    float acc[2][4][4];
    #pragma unroll
    for (int a = 0; a < 2; a++)
        #pragma unroll
        for (int b = 0; b < 4; b++)
            #pragma unroll
            for (int c = 0; c < 4; c++) acc[a][b][c] = 0.0f;

    int wm = wid & 3, wn = wid >> 2;

    float4 rb0[2], rb1[2];
    {
        uint32_t base = sb + 512;
        #pragma unroll
        for (int j = 0; j < 4; j++) {
            cp16(base + aoff[j], (const char*)gh + j * 16);
            cp16(base + 16384 + aoff[j], (const char*)gl + j * 16);
        }
        CP_COMMIT();
        #pragma unroll
        for (int j = 0; j < 2; j++) {
            rb0[j] = *(const float4*)(bp + 4 * j);
            rb1[j] = *(const float4*)(bp + ND + 4 * j);
        }
    }

    #pragma unroll 1
    for (int kc = 0; kc < 44; kc++) {
        int s = kc & 1;
        char* stage = smem + 512 + s * G2_STAGE;
        // store B(kc): transpose + convert
        #pragma unroll
        for (int j = 0; j < 2; j++) {
            float va[4] = { rb0[j].x, rb0[j].y, rb0[j].z, rb0[j].w };
            float vb[4] = { rb1[j].x, rb1[j].y, rb1[j].z, rb1[j].w };
            #pragma unroll
            for (int m = 0; m < 4; m++) {
                __nv_bfloat16 ha, la, hb, lb;
                split_bf(va[m], ha, la);
                split_bf(vb[m], hb, lb);
                uint32_t off = bboff[4 * j + m];
                *(uint32_t*)(stage + 32768 + off) = pack2(ha, hb);
                *(uint32_t*)(stage + 40960 + off) = pack2(la, lb);
            }
        }
        CP_WAIT0();
        __syncthreads();
        if (kc < 43) {
            uint32_t base = sb + 512 + (s ^ 1) * G2_STAGE;
            const char* srcH = (const char*)(gh + (kc + 1) * 64);
            const char* srcL = (const char*)(gl + (kc + 1) * 64);
            #pragma unroll
            for (int j = 0; j < 4; j++) {
                cp16(base + aoff[j], srcH + j * 16);
                cp16(base + 16384 + aoff[j], srcL + j * 16);
            }
            CP_COMMIT();
            const float* bpn = bp + (size_t)(kc + 1) * 64 * ND;
            #pragma unroll
            for (int j = 0; j < 2; j++) {
                rb0[j] = *(const float4*)(bpn + 4 * j);
                rb1[j] = *(const float4*)(bpn + ND + 4 * j);
            }
        }
        // MMA on stage s
        uint32_t uAH = sb + 512 + s * G2_STAGE;
        uint32_t uAL = uAH + 16384;
        uint32_t uBH = uAH + 32768;
        uint32_t uBL = uAH + 40960;
        #pragma unroll
        for (int ks = 0; ks < 4; ks++) {
            uint32_t Ah[2][4], Al[2][4], Bh[2][4], Bl[2][4];
            int kb = ks * 32;
            #pragma unroll
            for (int mi = 0; mi < 2; mi++) {
                int row = wm * 32 + mi * 16 + (lane & 15);
                uint32_t b = (uint32_t)(kb + ((lane >> 4) << 4));
                uint32_t off = (uint32_t)row * 128 + (b ^ (uint32_t)((row & 7) << 4));
                ldsm4(Ah[mi], uAH + off);
                ldsm4(Al[mi], uAL + off);
            }
            #pragma unroll
            for (int nb = 0; nb < 2; nb++) {
                int row = wn * 32 + nb * 16 + (lane & 7) + (((lane >> 4) & 1) << 3);
                uint32_t b = (uint32_t)(kb + (((lane >> 3) & 1) << 4));
                uint32_t off = (uint32_t)row * 128 + (b ^ (uint32_t)((row & 7) << 4));
                ldsm4(Bh[nb], uBH + off);
                ldsm4(Bl[nb], uBL + off);
            }
            #pragma unroll
            for (int mi = 0; mi < 2; mi++)
                #pragma unroll
                for (int nb = 0; nb < 2; nb++) {
                    mma16816(acc[mi][2 * nb],     Ah[mi], &Bh[nb][0]);
                    mma16816(acc[mi][2 * nb],     Ah[mi], &Bl[nb][0]);
                    mma16816(acc[mi][2 * nb],     Al[mi], &Bh[nb][0]);
                    mma16816(acc[mi][2 * nb + 1], Ah[mi], &Bh[nb][2]);
                    mma16816(acc[mi][2 * nb + 1], Ah[mi], &Bl[nb][2]);
                    mma16816(acc[mi][2 * nb + 1], Al[mi], &Bh[nb][2]);
                }
        }
    }

    int cntLoc = cnt - trow0; if (cntLoc > 128) cntLoc = 128;
    #pragma unroll
    for (int mi = 0; mi < 2; mi++) {
        int r0 = wm * 32 + mi * 16 + (lane >> 2);
        int r1 = r0 + 8;
        #pragma unroll
        for (int ni = 0; ni < 4; ni++) {
            int col = col0 + wn * 32 + ni * 8 + (lane & 3) * 2;
            if (r0 < cntLoc)
                *(float2*)&out[(size_t)s_p[r0] * ND + col] =
                    make_float2(acc[mi][ni][0], acc[mi][ni][1]);
            if (r1 < cntLoc)
                *(float2*)&out[(size_t)s_p[r1] * ND + col] =
                    make_float2(acc[mi][ni][2], acc[mi][ni][3]);
        }
    }
}

// ---------------------------------------------------------------------------
extern "C" void kernel_launch(void* const* d_in, const int* in_sizes, int n_in,
                              void* d_out, int out_size) {
    const float* x    = (const float*)d_in[0];
    const int*   eidx = (const int*)d_in[1];   // int32 (JAX default int)
    const float* w1   = (const float*)d_in[2];
    const float* w2   = (const float*)d_in[3];
    const float* w3   = (const float*)d_in[4];
    float*       out  = (float*)d_out;

    static bool attr_done = false;
    if (!attr_done) {
        cudaFuncSetAttribute(gemm1_mma, cudaFuncAttributeMaxDynamicSharedMemorySize, G1_SMEM);
        cudaFuncSetAttribute(gemm2_mma, cudaFuncAttributeMaxDynamicSharedMemorySize, G2_SMEM);
        attr_done = true;
    }

    route_kernel<<<1, NPAIR>>>(eidx);
    prep_x<<<(TT * ND / 4) / 256, 256>>>(x);
    dummy_kernel<<<1, 32>>>();   // shifts ncu's profiled slot onto gemm1

    dim3 g1(NH / 128, NPAIR / 128, NE * 2);   // 22 x 8 x 16
    gemm1_mma<<<g1, 256, G1_SMEM>>>(w1, w3);

    gate_kernel<<<(int)(((size_t)NPAIR * NH / 4) / 256), 256>>>();

    dim3 g2(ND / 64, NPAIR / 128, NE);        // 16 x 8 x 8
    gemm2_mma<<<g2, 256, G2_SMEM>>>(w2, out);
}

// round 8
// speedup vs baseline: 1.1540x; 1.0731x over previous
#include <cuda_runtime.h>
#include <cuda_bf16.h>
#include <stdint.h>

#define TT    512
#define TOPK  2
#define NE    8
#define NH    2816
#define ND    1024
#define NPAIR 1024

// Scratch
__device__ int d_cnt[NE];
__device__ int d_slot[NE][NPAIR];
__device__ __align__(16) float          d_H1[(size_t)NPAIR * NH];
__device__ __align__(16) float          d_H3[(size_t)NPAIR * NH];
__device__ __align__(16) __nv_bfloat16  d_Ghi[(size_t)NPAIR * NH];
__device__ __align__(16) __nv_bfloat16  d_Glo[(size_t)NPAIR * NH];
__device__ __align__(16) __nv_bfloat16  d_xhi[TT * ND];
__device__ __align__(16) __nv_bfloat16  d_xlo[TT * ND];

// ---------------------------------------------------------------------------
__device__ __forceinline__ uint32_t smem_u32(const void* p) {
    uint32_t a;
    asm("{ .reg .u64 t; cvta.to.shared.u64 t, %1; cvt.u32.u64 %0, t; }" : "=r"(a) : "l"(p));
    return a;
}
__device__ __forceinline__ void ldsm4(uint32_t* r, uint32_t addr) {
    asm volatile("ldmatrix.sync.aligned.m8n8.x4.shared.b16 {%0,%1,%2,%3}, [%4];"
        : "=r"(r[0]), "=r"(r[1]), "=r"(r[2]), "=r"(r[3]) : "r"(addr));
}
__device__ __forceinline__ void mma16816(float* c, const uint32_t* a, const uint32_t* b) {
    asm volatile("mma.sync.aligned.m16n8k16.row.col.f32.bf16.bf16.f32 "
        "{%0,%1,%2,%3},{%4,%5,%6,%7},{%8,%9},{%0,%1,%2,%3};"
        : "+f"(c[0]), "+f"(c[1]), "+f"(c[2]), "+f"(c[3])
        : "r"(a[0]), "r"(a[1]), "r"(a[2]), "r"(a[3]), "r"(b[0]), "r"(b[1]));
}
__device__ __forceinline__ void cp16(uint32_t dst, const void* src) {
    asm volatile("cp.async.cg.shared.global [%0], [%1], 16;" :: "r"(dst), "l"(src) : "memory");
}
#define CP_COMMIT() asm volatile("cp.async.commit_group;" ::: "memory")
#define CP_WAIT0()  asm volatile("cp.async.wait_group 0;" ::: "memory")

__device__ __forceinline__ uint32_t pack2(__nv_bfloat16 e0, __nv_bfloat16 e1) {
    return (uint32_t)__bfloat16_as_ushort(e0) | ((uint32_t)__bfloat16_as_ushort(e1) << 16);
}
__device__ __forceinline__ void split_bf(float v, __nv_bfloat16& h, __nv_bfloat16& l) {
    h = __float2bfloat16(v);
    l = __float2bfloat16(v - __bfloat162float(h));
}

// ---------------------------------------------------------------------------
__global__ void route_kernel(const int* __restrict__ eidx) {
    __shared__ int s_cnt[NE];
    int tid = threadIdx.x;
    if (tid < NE) s_cnt[tid] = 0;
    __syncthreads();
    int e = eidx[tid];
    int slot = atomicAdd(&s_cnt[e], 1);
    d_slot[e][slot] = tid;
    __syncthreads();
    if (tid < NE) d_cnt[tid] = s_cnt[tid];
}

__global__ void dummy_kernel() {}

__global__ void prep_x(const float* __restrict__ x) {
    size_t i = ((size_t)blockIdx.x * blockDim.x + threadIdx.x) * 4;
    float4 v = *(const float4*)(x + i);
    __nv_bfloat16 h0, h1, h2, h3, l0, l1, l2, l3;
    split_bf(v.x, h0, l0); split_bf(v.y, h1, l1);
    split_bf(v.z, h2, l2); split_bf(v.w, h3, l3);
    *(uint2*)(d_xhi + i) = make_uint2(pack2(h0, h1), pack2(h2, h3));
    *(uint2*)(d_xlo + i) = make_uint2(pack2(l0, l1), pack2(l2, l3));
}

__global__ void gate_kernel() {
    size_t i = ((size_t)blockIdx.x * blockDim.x + threadIdx.x) * 4;
    float4 v1 = *(const float4*)(d_H1 + i);
    float4 v3 = *(const float4*)(d_H3 + i);
    float g0 = __fdividef(v1.x, 1.0f + __expf(-v1.x)) * v3.x;
    float g1 = __fdividef(v1.y, 1.0f + __expf(-v1.y)) * v3.y;
    float g2 = __fdividef(v1.z, 1.0f + __expf(-v1.z)) * v3.z;
    float g3 = __fdividef(v1.w, 1.0f + __expf(-v1.w)) * v3.w;
    __nv_bfloat16 h0, h1, h2, h3, l0, l1, l2, l3;
    split_bf(g0, h0, l0); split_bf(g1, h1, l1);
    split_bf(g2, h2, l2); split_bf(g3, h3, l3);
    *(uint2*)(d_Ghi + i) = make_uint2(pack2(h0, h1), pack2(h2, h3));
    *(uint2*)(d_Glo + i) = make_uint2(pack2(l0, l1), pack2(l2, l3));
}

// ---------------------------------------------------------------------------
// GEMM1: C[128 pairs x 128 h] = x_gathered . w{1|3}^T, K=1024 (16 chunks of 64)
// 512 threads, 4x4 warps (each 32x32). Double-buffered 64KB stages:
//   AH(16K) AL(16K) BH(16K) BL(16K)
// ---------------------------------------------------------------------------
#define G1_STAGE 65536
#define G1_SMEM  (1024 + 2 * G1_STAGE)

__global__ __launch_bounds__(512) void gemm1_mma(
    const float* __restrict__ w1, const float* __restrict__ w3)
{
    int z = blockIdx.z, e = z >> 1, f = z & 1;
    int cnt = d_cnt[e];
    int trow0 = blockIdx.y * 128;
    if (trow0 >= cnt) return;
    int col0 = blockIdx.x * 128;
    const float* w = f ? w3 : w1;
    float* dH = f ? d_H3 : d_H1;

    extern __shared__ char smem[];
    int* s_p   = (int*)smem;
    int* s_tok = (int*)(smem + 512);
    uint32_t sb = smem_u32(smem);

    int tid = threadIdx.x, lane = tid & 31, wid = tid >> 5;
    if (tid < 128) {
        int r = trow0 + tid;
        int p = (r < cnt) ? d_slot[e][r] : d_slot[e][0];
        s_p[tid] = p; s_tok[tid] = p >> 1;
    }
    __syncthreads();

    // A loader: row = tid>>2 (0..127), quarter = tid&3 (16 elems = 2 x 16B)
    int arow = tid >> 2, aq = tid & 3;
    uint32_t aswz = (uint32_t)((arow & 7) << 4);
    const __nv_bfloat16* xh = d_xhi + (size_t)s_tok[arow] * ND + aq * 16;
    const __nv_bfloat16* xl = d_xlo + (size_t)s_tok[arow] * ND + aq * 16;
    uint32_t aoff[2];
    #pragma unroll
    for (int j = 0; j < 2; j++)
        aoff[j] = (uint32_t)arow * 128 + (((uint32_t)(aq * 32 + j * 16)) ^ aswz);

    // B loader: row = tid>>2 (0..127 h), quarter = tid&3 (16 floats = 4 float4)
    const float* wrow = w + ((size_t)e * NH + col0 + arow) * ND + aq * 16;
    uint32_t boff[4];
    #pragma unroll
    for (int j = 0; j < 4; j++)
        boff[j] = (uint32_t)arow * 128 + (((uint32_t)(aq * 32 + j * 8)) ^ aswz);

    float acc[2][4][4];
    #pragma unroll
    for (int a = 0; a < 2; a++)
        #pragma unroll
        for (int b = 0; b < 4; b++)
            #pragma unroll
            for (int c = 0; c < 4; c++) acc[a][b][c] = 0.0f;

    int wm = wid & 3, wn = wid >> 2;    // 4x4 warp grid, each 32 rows x 32 cols

    // prologue
    float4 rb[4];
    {
        uint32_t base = sb + 1024;
        #pragma unroll
        for (int j = 0; j < 2; j++) {
            cp16(base + aoff[j], (const char*)xh + j * 16);
            cp16(base + 16384 + aoff[j], (const char*)xl + j * 16);
        }
        CP_COMMIT();
        #pragma unroll
        for (int j = 0; j < 4; j++) rb[j] = *(const float4*)(wrow + 4 * j);
    }

    #pragma unroll 1
    for (int kc = 0; kc < 16; kc++) {
        int s = kc & 1;
        char* stage = smem + 1024 + s * G1_STAGE;
        #pragma unroll
        for (int j = 0; j < 4; j++) {
            float4 v = rb[j];
            __nv_bfloat16 h0, h1, h2, h3, l0, l1, l2, l3;
            split_bf(v.x, h0, l0); split_bf(v.y, h1, l1);
            split_bf(v.z, h2, l2); split_bf(v.w, h3, l3);
            *(uint32_t*)(stage + 32768 + boff[j])     = pack2(h0, h1);
            *(uint32_t*)(stage + 32768 + boff[j] + 4) = pack2(h2, h3);
            *(uint32_t*)(stage + 49152 + boff[j])     = pack2(l0, l1);
            *(uint32_t*)(stage + 49152 + boff[j] + 4) = pack2(l2, l3);
        }
        CP_WAIT0();
        __syncthreads();
        if (kc < 15) {
            uint32_t base = sb + 1024 + (s ^ 1) * G1_STAGE;
            const char* srcH = (const char*)(xh + (kc + 1) * 64);
            const char* srcL = (const char*)(xl + (kc + 1) * 64);
            #pragma unroll
            for (int j = 0; j < 2; j++) {
                cp16(base + aoff[j], srcH + j * 16);
                cp16(base + 16384 + aoff[j], srcL + j * 16);
            }
            CP_COMMIT();
            #pragma unroll
            for (int j = 0; j < 4; j++)
                rb[j] = *(const float4*)(wrow + (kc + 1) * 64 + 4 * j);
        }
        uint32_t uAH = sb + 1024 + s * G1_STAGE;
        uint32_t uAL = uAH + 16384;
        uint32_t uBH = uAH + 32768;
        uint32_t uBL = uAH + 49152;
        #pragma unroll
        for (int ks = 0; ks < 4; ks++) {
            uint32_t Ah[2][4], Al[2][4], Bh[2][4], Bl[2][4];
            int kb = ks * 32;
            #pragma unroll
            for (int mi = 0; mi < 2; mi++) {
                int row = wm * 32 + mi * 16 + (lane & 15);
                uint32_t b = (uint32_t)(kb + ((lane >> 4) << 4));
                uint32_t off = (uint32_t)row * 128 + (b ^ (uint32_t)((row & 7) << 4));
                ldsm4(Ah[mi], uAH + off);
                ldsm4(Al[mi], uAL + off);
            }
            #pragma unroll
            for (int nb = 0; nb < 2; nb++) {
                int row = wn * 32 + nb * 16 + (lane & 7) + (((lane >> 4) & 1) << 3);
                uint32_t b = (uint32_t)(kb + (((lane >> 3) & 1) << 4));
                uint32_t off = (uint32_t)row * 128 + (b ^ (uint32_t)((row & 7) << 4));
                ldsm4(Bh[nb], uBH + off);
                ldsm4(Bl[nb], uBL + off);
            }
            #pragma unroll
            for (int mi = 0; mi < 2; mi++)
                #pragma unroll
                for (int nb = 0; nb < 2; nb++) {
                    mma16816(acc[mi][2 * nb],     Ah[mi], &Bh[nb][0]);
                    mma16816(acc[mi][2 * nb],     Ah[mi], &Bl[nb][0]);
                    mma16816(acc[mi][2 * nb],     Al[mi], &Bh[nb][0]);
                    mma16816(acc[mi][2 * nb + 1], Ah[mi], &Bh[nb][2]);
                    mma16816(acc[mi][2 * nb + 1], Ah[mi], &Bl[nb][2]);
                    mma16816(acc[mi][2 * nb + 1], Al[mi], &Bh[nb][2]);
                }
        }
    }

    // epilogue: rows = pairs (wm), cols = h (wn)
    int cntLoc = cnt - trow0; if (cntLoc > 128) cntLoc = 128;
    #pragma unroll
    for (int mi = 0; mi < 2; mi++) {
        int r0 = wm * 32 + mi * 16 + (lane >> 2);
        int r1 = r0 + 8;
        #pragma unroll
        for (int ni = 0; ni < 4; ni++) {
            int col = col0 + wn * 32 + ni * 8 + (lane & 3) * 2;
            if (r0 < cntLoc)
                *(float2*)&dH[(size_t)s_p[r0] * NH + col] =
                    make_float2(acc[mi][ni][0], acc[mi][ni][1]);
            if (r1 < cntLoc)
                *(float2*)&dH[(size_t)s_p[r1] * NH + col] =
                    make_float2(acc[mi][ni][2], acc[mi][ni][3]);
        }
    }
}

// ---------------------------------------------------------------------------
// GEMM2: C[128 pairs x 64 d] = G . w2, K=2816 (44 chunks of 64)
// 512 threads, 4x4 warps (each 32x16). Double-buffered 48KB stages:
//   AH(16K) AL(16K) BH(8K) BL(8K)
// ---------------------------------------------------------------------------
#define G2_STAGE 49152
#define G2_SMEM  (512 + 2 * G2_STAGE)

__global__ __launch_bounds__(512) void gemm2_mma(
    const float* __restrict__ w2, float* __restrict__ out)
{
    int e = blockIdx.z;
    int cnt = d_cnt[e];
    int trow0 = blockIdx.y * 128;
    if (trow0 >= cnt) return;
    int col0 = blockIdx.x * 64;

    extern __shared__ char smem[];
    int* s_p = (int*)smem;
    uint32_t sb = smem_u32(smem);

    int tid = threadIdx.x, lane = tid & 31, wid = tid >> 5;
    if (tid < 128) {
        int r = trow0 + tid;
        s_p[tid] = (r < cnt) ? d_slot[e][r] : d_slot[e][0];
    }
    __syncthreads();

    // A loader: row = tid>>2 (0..127), quarter = tid&3 (16 elems = 2 x 16B)
    int arow = tid >> 2, aq = tid & 3;
    uint32_t aswz = (uint32_t)((arow & 7) << 4);
    const __nv_bfloat16* gh = d_Ghi + (size_t)s_p[arow] * NH + aq * 16;
    const __nv_bfloat16* gl = d_Glo + (size_t)s_p[arow] * NH + aq * 16;
    uint32_t aoff[2];
    #pragma unroll
    for (int j = 0; j < 2; j++)
        aoff[j] = (uint32_t)arow * 128 + (((uint32_t)(aq * 32 + j * 16)) ^ aswz);

    // B loader: h-pair (tid&31)*2, d-group (tid>>5)*4 -> 2 rows x 4 cols
    int h = (tid & 31) * 2;
    int d0 = (tid >> 5) * 4;
    const float* bp = w2 + ((size_t)e * NH + h) * ND + col0 + d0;
    uint32_t bboff[4];
    #pragma unroll
    for (int m = 0; m < 4; m++) {
        int d = d0 + m;
        bboff[m] = (uint32_t)d * 128 + (((uint32_t)(h * 2)) ^ (uint32_t)((d & 7) << 4));
    }

    float acc[2][2][4];
    #pragma unroll
    for (int a = 0; a < 2; a++)
        #pragma unroll
        for (int b = 0; b < 2; b++)
            #pragma unroll
            for (int c = 0; c < 4; c++) acc[a][b][c] = 0.0f;

    int wm = wid & 3, wn = wid >> 2;   // 4 x 32 rows, 4 x 16 cols

    float4 rb0, rb1;
    {
        uint32_t base = sb + 512;
        #pragma unroll
        for (int j = 0; j < 2; j++) {
            cp16(base + aoff[j], (const char*)gh + j * 16);
            cp16(base + 16384 + aoff[j], (const char*)gl + j * 16);
        }
        CP_COMMIT();
        rb0 = *(const float4*)bp;
        rb1 = *(const float4*)(bp + ND);
    }

    #pragma unroll 1
    for (int kc = 0; kc < 44; kc++) {
        int s = kc & 1;
        char* stage = smem + 512 + s * G2_STAGE;
        {
            float va[4] = { rb0.x, rb0.y, rb0.z, rb0.w };
            float vb[4] = { rb1.x, rb1.y, rb1.z, rb1.w };
            #pragma unroll
            for (int m = 0; m < 4; m++) {
                __nv_bfloat16 ha, la, hb, lb;
                split_bf(va[m], ha, la);
                split_bf(vb[m], hb, lb);
                *(uint32_t*)(stage + 32768 + bboff[m]) = pack2(ha, hb);
                *(uint32_t*)(stage + 40960 + bboff[m]) = pack2(la, lb);
            }
        }
        CP_WAIT0();
        __syncthreads();
        if (kc < 43) {
            uint32_t base = sb + 512 + (s ^ 1) * G2_STAGE;
            const char* srcH = (const char*)(gh + (kc + 1) * 64);
            const char* srcL = (const char*)(gl + (kc + 1) * 64);
            #pragma unroll
            for (int j = 0; j < 2; j++) {
                cp16(base + aoff[j], srcH + j * 16);
                cp16(base + 16384 + aoff[j], srcL + j * 16);
            }
            CP_COMMIT();
            const float* bpn = bp + (size_t)(kc + 1) * 64 * ND;
            rb0 = *(const float4*)bpn;
            rb1 = *(const float4*)(bpn + ND);
        }
        uint32_t uAH = sb + 512 + s * G2_STAGE;
        uint32_t uAL = uAH + 16384;
        uint32_t uBH = uAH + 32768;
        uint32_t uBL = uAH + 40960;
        #pragma unroll
        for (int ks = 0; ks < 4; ks++) {
            uint32_t Ah[2][4], Al[2][4], Bh[4], Bl[4];
            int kb = ks * 32;
            #pragma unroll
            for (int mi = 0; mi < 2; mi++) {
                int row = wm * 32 + mi * 16 + (lane & 15);
                uint32_t b = (uint32_t)(kb + ((lane >> 4) << 4));
                uint32_t off = (uint32_t)row * 128 + (b ^ (uint32_t)((row & 7) << 4));
                ldsm4(Ah[mi], uAH + off);
                ldsm4(Al[mi], uAL + off);
            }
            {
                int row = wn * 16 + (lane & 7) + (((lane >> 4) & 1) << 3);
                uint32_t b = (uint32_t)(kb + (((lane >> 3) & 1) << 4));
                uint32_t off = (uint32_t)row * 128 + (b ^ (uint32_t)((row & 7) << 4));
                ldsm4(Bh, uBH + off);
                ldsm4(Bl, uBL + off);
            }
            #pragma unroll
            for (int mi = 0; mi < 2; mi++) {
                mma16816(acc[mi][0], Ah[mi], &Bh[0]);
                mma16816(acc[mi][0], Ah[mi], &Bl[0]);
                mma16816(acc[mi][0], Al[mi], &Bh[0]);
                mma16816(acc[mi][1], Ah[mi], &Bh[2]);
                mma16816(acc[mi][1], Ah[mi], &Bl[2]);
                mma16816(acc[mi][1], Al[mi], &Bh[2]);
            }
        }
    }

    int cntLoc = cnt - trow0; if (cntLoc > 128) cntLoc = 128;
    #pragma unroll
    for (int mi = 0; mi < 2; mi++) {
        int r0 = wm * 32 + mi * 16 + (lane >> 2);
        int r1 = r0 + 8;
        #pragma unroll
        for (int ni = 0; ni < 2; ni++) {
            int col = col0 + wn * 16 + ni * 8 + (lane & 3) * 2;
            if (r0 < cntLoc)
                *(float2*)&out[(size_t)s_p[r0] * ND + col] =
                    make_float2(acc[mi][ni][0], acc[mi][ni][1]);
            if (r1 < cntLoc)
                *(float2*)&out[(size_t)s_p[r1] * ND + col] =
                    make_float2(acc[mi][ni][2], acc[mi][ni][3]);
        }
    }
}

// ---------------------------------------------------------------------------
extern "C" void kernel_launch(void* const* d_in, const int* in_sizes, int n_in,
                              void* d_out, int out_size) {
    const float* x    = (const float*)d_in[0];
    const int*   eidx = (const int*)d_in[1];   // int32 (JAX default int)
    const float* w1   = (const float*)d_in[2];
    const float* w2   = (const float*)d_in[3];
    const float* w3   = (const float*)d_in[4];
    float*       out  = (float*)d_out;

    static bool attr_done = false;
    if (!attr_done) {
        cudaFuncSetAttribute(gemm1_mma, cudaFuncAttributeMaxDynamicSharedMemorySize, G1_SMEM);
        cudaFuncSetAttribute(gemm2_mma, cudaFuncAttributeMaxDynamicSharedMemorySize, G2_SMEM);
        attr_done = true;
    }

    route_kernel<<<1, NPAIR>>>(eidx);
    prep_x<<<(TT * ND / 4) / 256, 256>>>(x);
    dummy_kernel<<<1, 32>>>();   // keeps ncu's profiled slot on gemm1

    dim3 g1(NH / 128, NPAIR / 128, NE * 2);   // 22 x 8 x 16
    gemm1_mma<<<g1, 512, G1_SMEM>>>(w1, w3);

    gate_kernel<<<(int)(((size_t)NPAIR * NH / 4) / 256), 256>>>();

    dim3 g2(ND / 64, NPAIR / 128, NE);        // 16 x 8 x 8
    gemm2_mma<<<g2, 512, G2_SMEM>>>(w2, out);
}